// round 1
// baseline (speedup 1.0000x reference)
#include <cuda_runtime.h>
#include <math.h>

#define B_SZ    2
#define L_SEQ   4096
#define DMODEL  768
#define DINNER  1536
#define DT_RANK 48
#define D_STATE 16
#define NROWS   (B_SZ * L_SEQ)          /* 8192 */
#define XDBL_N  (DT_RANK + 2 * D_STATE) /* 80   */

// ---------------- scratch (no cudaMalloc allowed) ----------------
__device__ float g_xz[(size_t)NROWS * 2 * DINNER];   // 96 MB  [row][3072] (x | z)
__device__ float g_xc[(size_t)NROWS * DINNER];       // 48 MB  conv+silu output (u)
__device__ float g_xdbl[(size_t)NROWS * XDBL_N];     // 2.5 MB [row][80] (dt | B | C)
__device__ float g_delta[(size_t)NROWS * DINNER];    // 48 MB
__device__ float g_y[(size_t)NROWS * DINNER];        // 48 MB  gated scan output

// =================================================================
// Generic tiled SIMT fp32 GEMM:  C[M,N] = A[M,K(lda)] * B[K,N]
// EP: 0 = none, 1 = softplus(acc + bias[col])
// =================================================================
template <int BM, int BN, int BK, int TM, int TN, int EP>
__global__ __launch_bounds__(256) void gemm_kernel(
    const float* __restrict__ A, const float* __restrict__ Bm,
    float* __restrict__ C, int M, int N, int K, int lda,
    const float* __restrict__ bias)
{
    __shared__ float As[BK][BM + 4];   // transposed A tile, padded (align + fewer conflicts)
    __shared__ float Bs[BK][BN];

    const int bm  = blockIdx.y * BM;
    const int bn  = blockIdx.x * BN;
    const int tid = threadIdx.x;
    const int trow = (tid >> 4) * TM;
    const int tcol = (tid & 15) * TN;

    float acc[TM][TN];
#pragma unroll
    for (int i = 0; i < TM; i++)
#pragma unroll
        for (int j = 0; j < TN; j++) acc[i][j] = 0.f;

    const bool fullN = (bn + BN <= N);

    for (int k0 = 0; k0 < K; k0 += BK) {
        // ---- load A tile (BM x BK), store transposed ----
#pragma unroll
        for (int i = 0; i < (BM * BK / 4) / 256; i++) {
            int idx4 = tid + i * 256;
            int r = idx4 >> 2;
            int c = (idx4 & 3) << 2;
            float4 v = *(const float4*)(A + (size_t)(bm + r) * lda + k0 + c);
            As[c + 0][r] = v.x; As[c + 1][r] = v.y;
            As[c + 2][r] = v.z; As[c + 3][r] = v.w;
        }
        // ---- load B tile (BK x BN) ----
#pragma unroll
        for (int i = 0; i < (BK * BN / 4) / 256; i++) {
            int idx4 = tid + i * 256;
            int r = idx4 / (BN / 4);
            int c = (idx4 % (BN / 4)) << 2;
            float4 v;
            if (fullN) {
                v = *(const float4*)(Bm + (size_t)(k0 + r) * N + bn + c);
            } else {
                v.x = (bn + c + 0 < N) ? Bm[(size_t)(k0 + r) * N + bn + c + 0] : 0.f;
                v.y = (bn + c + 1 < N) ? Bm[(size_t)(k0 + r) * N + bn + c + 1] : 0.f;
                v.z = (bn + c + 2 < N) ? Bm[(size_t)(k0 + r) * N + bn + c + 2] : 0.f;
                v.w = (bn + c + 3 < N) ? Bm[(size_t)(k0 + r) * N + bn + c + 3] : 0.f;
            }
            *(float4*)&Bs[r][c] = v;
        }
        __syncthreads();

#pragma unroll
        for (int kk = 0; kk < BK; kk++) {
            float a[TM], b[TN];
#pragma unroll
            for (int i = 0; i < TM; i += 4)
                *(float4*)&a[i] = *(const float4*)&As[kk][trow + i];
#pragma unroll
            for (int j = 0; j < TN; j += 4)
                *(float4*)&b[j] = *(const float4*)&Bs[kk][tcol + j];
#pragma unroll
            for (int i = 0; i < TM; i++)
#pragma unroll
                for (int j = 0; j < TN; j++)
                    acc[i][j] = fmaf(a[i], b[j], acc[i][j]);
        }
        __syncthreads();
    }

    // ---- epilogue + store ----
    if (fullN) {
#pragma unroll
        for (int i = 0; i < TM; i++) {
            size_t row = (size_t)(bm + trow + i);
#pragma unroll
            for (int j = 0; j < TN; j += 4) {
                float4 v;
                float* pv = &v.x;
#pragma unroll
                for (int q = 0; q < 4; q++) {
                    float t = acc[i][j + q];
                    if (EP == 1) {
                        t += bias[bn + tcol + j + q];
                        t = (t > 20.f) ? t : log1pf(expf(t));
                    }
                    pv[q] = t;
                }
                *(float4*)(C + row * N + bn + tcol + j) = v;
            }
        }
    } else {
#pragma unroll
        for (int i = 0; i < TM; i++) {
            size_t row = (size_t)(bm + trow + i);
#pragma unroll
            for (int j = 0; j < TN; j++) {
                int col = bn + tcol + j;
                if (col < N) {
                    float t = acc[i][j];
                    if (EP == 1) {
                        t += bias[col];
                        t = (t > 20.f) ? t : log1pf(expf(t));
                    }
                    C[row * N + col] = t;
                }
            }
        }
    }
}

// =================================================================
// Depthwise causal conv (width 4) + bias + SiLU.
// reads x = g_xz[:, 0:1536], writes g_xc (layout [b,l,d]).
// grid: (DINNER/256, L/64, B), block 256
// =================================================================
__global__ __launch_bounds__(256) void conv_silu_kernel(
    const float* __restrict__ cw, const float* __restrict__ cb)
{
    const int d  = blockIdx.x * 256 + threadIdx.x;
    const int b  = blockIdx.z;
    const int l0 = blockIdx.y * 64;

    const float w0 = cw[d * 4 + 0], w1 = cw[d * 4 + 1];
    const float w2 = cw[d * 4 + 2], w3 = cw[d * 4 + 3];
    const float bi = cb[d];

    const float* xp = g_xz + ((size_t)(b * L_SEQ + l0)) * (2 * DINNER) + d;
    float*       op = g_xc + ((size_t)(b * L_SEQ + l0)) * DINNER + d;

    float xm3, xm2, xm1;
    if (l0 == 0) {
        xm3 = xm2 = xm1 = 0.f;
    } else {
        xm3 = xp[-(ptrdiff_t)3 * 2 * DINNER];
        xm2 = xp[-(ptrdiff_t)2 * 2 * DINNER];
        xm1 = xp[-(ptrdiff_t)1 * 2 * DINNER];
    }
#pragma unroll 4
    for (int i = 0; i < 64; i++) {
        float x0 = xp[0];
        float v  = fmaf(w0, xm3, fmaf(w1, xm2, fmaf(w2, xm1, fmaf(w3, x0, bi))));
        *op = v / (1.f + __expf(-v));           // silu
        xm3 = xm2; xm2 = xm1; xm1 = x0;
        xp += 2 * DINNER; op += DINNER;
    }
}

// =================================================================
// Selective scan + skip (u*D) + z-gating.
// One warp handles 2 channels; lanes 0-15 -> (d0, n), lanes 16-31 -> (d1, n).
// h_{t} = exp(delta*A)*h_{t-1} + delta*u*B_t ;  y_t = sum_n h*C_t
// 4-deep register prefetch to hide load latency.
// 1536 warps total: grid 192 x 256 threads.
// =================================================================
__global__ __launch_bounds__(256) void scan_kernel(
    const float* __restrict__ A_log, const float* __restrict__ Dp)
{
    const int wid  = blockIdx.x * 8 + (threadIdx.x >> 5);
    const int lane = threadIdx.x & 31;
    const int b    = wid / (DINNER / 2);
    const int dpr  = wid % (DINNER / 2);
    const int half = lane >> 4;
    const int n    = lane & 15;
    const int d    = dpr * 2 + half;

    const float A  = -__expf(A_log[d * D_STATE + n]);
    const float Dd = Dp[d];

    const size_t base = (size_t)b * L_SEQ;
    const float* dp = g_delta + base * DINNER + d;
    const float* up = g_xc    + base * DINNER + d;
    const float* bp = g_xdbl  + base * XDBL_N + DT_RANK + n;
    const float* cp = g_xdbl  + base * XDBL_N + DT_RANK + D_STATE + n;
    const float* zp = g_xz    + base * (2 * DINNER) + DINNER + d;
    float*       yp = g_y     + base * DINNER + d;

    float pd[4], pu[4], pb[4], pc[4];
#pragma unroll
    for (int g = 0; g < 4; g++) {
        pd[g] = __ldg(dp + g * DINNER);
        pu[g] = __ldg(up + g * DINNER);
        pb[g] = __ldg(bp + g * XDBL_N);
        pc[g] = __ldg(cp + g * XDBL_N);
    }

    float h = 0.f;
    for (int t0 = 0; t0 < L_SEQ; t0 += 4) {
        float cd[4], cu[4], cb_[4], cc[4];
#pragma unroll
        for (int g = 0; g < 4; g++) { cd[g]=pd[g]; cu[g]=pu[g]; cb_[g]=pb[g]; cc[g]=pc[g]; }

        dp += 4 * DINNER; up += 4 * DINNER; bp += 4 * XDBL_N; cp += 4 * XDBL_N;
        if (t0 + 4 < L_SEQ) {
#pragma unroll
            for (int g = 0; g < 4; g++) {
                pd[g] = __ldg(dp + g * DINNER);
                pu[g] = __ldg(up + g * DINNER);
                pb[g] = __ldg(bp + g * XDBL_N);
                pc[g] = __ldg(cp + g * XDBL_N);
            }
        }

#pragma unroll
        for (int g = 0; g < 4; g++) {
            float dt = cd[g], u = cu[g];
            float dA = __expf(dt * A);
            h = fmaf(dA, h, dt * u * cb_[g]);
            float p = h * cc[g];
            p += __shfl_xor_sync(0xffffffffu, p, 1);
            p += __shfl_xor_sync(0xffffffffu, p, 2);
            p += __shfl_xor_sync(0xffffffffu, p, 4);
            p += __shfl_xor_sync(0xffffffffu, p, 8);
            if (n == 0) {
                float z  = __ldg(zp + g * (2 * DINNER));
                float sz = z / (1.f + __expf(-z));
                yp[(size_t)g * DINNER] = (p + u * Dd) * sz;
            }
        }
        zp += (size_t)4 * 2 * DINNER; yp += (size_t)4 * DINNER;
    }
}

// =================================================================
extern "C" void kernel_launch(void* const* d_in, const int* in_sizes, int n_in,
                              void* d_out, int out_size)
{
    const float* hidden = (const float*)d_in[0];
    const float* Win    = (const float*)d_in[1];
    const float* conv_w = (const float*)d_in[2];
    const float* conv_b = (const float*)d_in[3];
    const float* Wx     = (const float*)d_in[4];
    const float* Wdt    = (const float*)d_in[5];
    const float* bdt    = (const float*)d_in[6];
    const float* A_log  = (const float*)d_in[7];
    const float* Dp     = (const float*)d_in[8];
    const float* Wout   = (const float*)d_in[9];
    float* out = (float*)d_out;

    float *xz, *xc, *xdbl, *delta, *y;
    cudaGetSymbolAddress((void**)&xz,    g_xz);
    cudaGetSymbolAddress((void**)&xc,    g_xc);
    cudaGetSymbolAddress((void**)&xdbl,  g_xdbl);
    cudaGetSymbolAddress((void**)&delta, g_delta);
    cudaGetSymbolAddress((void**)&y,     g_y);

    // 1) in-projection: xz = hidden @ Win   [8192,768]x[768,3072]
    gemm_kernel<128,128,16,8,8,0><<<dim3(2*DINNER/128, NROWS/128), 256>>>(
        hidden, Win, xz, NROWS, 2*DINNER, DMODEL, DMODEL, nullptr);

    // 2) depthwise conv + silu -> u
    conv_silu_kernel<<<dim3(DINNER/256, L_SEQ/64, B_SZ), 256>>>(conv_w, conv_b);

    // 3) x_dbl = u @ Wx   [8192,1536]x[1536,80]
    gemm_kernel<64,128,16,4,8,0><<<dim3(1, NROWS/64), 256>>>(
        xc, Wx, xdbl, NROWS, XDBL_N, DINNER, DINNER, nullptr);

    // 4) delta = softplus(x_dbl[:, :48] @ Wdt + bdt)   [8192,48]x[48,1536]
    gemm_kernel<128,128,16,8,8,1><<<dim3(DINNER/128, NROWS/128), 256>>>(
        xdbl, Wdt, delta, NROWS, DINNER, DT_RANK, XDBL_N, bdt);

    // 5) selective scan + skip + gating -> y
    scan_kernel<<<B_SZ * (DINNER/2) / 8, 256>>>(A_log, Dp);

    // 6) out-projection: out = y @ Wout   [8192,1536]x[1536,768]
    gemm_kernel<128,128,16,8,8,0><<<dim3(DMODEL/128, NROWS/128), 256>>>(
        y, Wout, out, NROWS, DMODEL, DINNER, DINNER, nullptr);
}

// round 3
// speedup vs baseline: 1.2400x; 1.2400x over previous
#include <cuda_runtime.h>
#include <cuda_bf16.h>
#include <math.h>
#include <stdint.h>

#define B_SZ    2
#define L_SEQ   4096
#define DMODEL  768
#define DINNER  1536
#define DT_RANK 48
#define D_STATE 16
#define NROWS   (B_SZ * L_SEQ)          /* 8192 */
#define XDBL_N  (DT_RANK + 2 * D_STATE) /* 80   */

// ---------------- fp32 scratch ----------------
__device__ __align__(16) float g_xz[(size_t)NROWS * 2 * DINNER];
__device__ __align__(16) float g_xc[(size_t)NROWS * DINNER];
__device__ __align__(16) float g_xdbl[(size_t)NROWS * XDBL_N];
__device__ __align__(16) float g_delta[(size_t)NROWS * DINNER];
__device__ __align__(16) float g_y[(size_t)NROWS * DINNER];

// ---------------- bf16 3-term packed operands ----------------
// A' = [A_hi | A_lo | A_hi] along K ; B' (transposed, [N,K'] K-major) = [B_hi | B_hi | B_lo]
__device__ __align__(128) __nv_bfloat16 g_Ain [(size_t)NROWS * 3 * DMODEL];
__device__ __align__(128) __nv_bfloat16 g_Bin [(size_t)(2*DINNER) * 3 * DMODEL];
__device__ __align__(128) __nv_bfloat16 g_Au  [(size_t)NROWS * 3 * DINNER];
__device__ __align__(128) __nv_bfloat16 g_Bx  [(size_t)128 * 3 * DINNER];
__device__ __align__(128) __nv_bfloat16 g_Adt [(size_t)NROWS * 3 * 64];
__device__ __align__(128) __nv_bfloat16 g_Bdt [(size_t)DINNER * 3 * 64];
__device__ __align__(128) __nv_bfloat16 g_Ay  [(size_t)NROWS * 3 * DINNER];
__device__ __align__(128) __nv_bfloat16 g_Bout[(size_t)DMODEL * 3 * DINNER];

// =================================================================
// PTX helpers (base ISA only — no sm_103a-gated features)
// =================================================================
static __device__ __forceinline__ uint32_t s2u(const void* p) {
    uint32_t a;
    asm("{ .reg .u64 t; cvta.to.shared.u64 t, %1; cvt.u32.u64 %0, t; }"
        : "=r"(a) : "l"(p));
    return a;
}
static __device__ __forceinline__ void cp16(uint32_t d, const void* s) {
    asm volatile("cp.async.cg.shared.global [%0], [%1], 16;" :: "r"(d), "l"(s));
}
static __device__ __forceinline__ void cp_commit() {
    asm volatile("cp.async.commit_group;" ::: "memory");
}
template <int N> static __device__ __forceinline__ void cp_wait() {
    asm volatile("cp.async.wait_group %0;" :: "n"(N) : "memory");
}
#define LDSM4(r0, r1, r2, r3, addr) \
    asm volatile("ldmatrix.sync.aligned.m8n8.x4.shared.b16 {%0,%1,%2,%3}, [%4];" \
                 : "=r"(r0), "=r"(r1), "=r"(r2), "=r"(r3) : "r"(addr))

static __device__ __forceinline__ void mma_bf16(
    float& d0, float& d1, float& d2, float& d3,
    uint32_t a0, uint32_t a1, uint32_t a2, uint32_t a3,
    uint32_t b0, uint32_t b1)
{
    asm volatile(
        "mma.sync.aligned.m16n8k16.row.col.f32.bf16.bf16.f32 "
        "{%0,%1,%2,%3}, {%4,%5,%6,%7}, {%8,%9}, {%0,%1,%2,%3};"
        : "+f"(d0), "+f"(d1), "+f"(d2), "+f"(d3)
        : "r"(a0), "r"(a1), "r"(a2), "r"(a3), "r"(b0), "r"(b1));
}

template <int EP>
static __device__ __forceinline__ float epilogue_op(float t, const float* bias, int col) {
    if (EP == 1) {
        t += bias[col];
        t = (t > 20.f) ? t : log1pf(expf(t));
    }
    return t;
}

// =================================================================
// HMMA GEMM:  C[M, N] = A'[M, K'] * B'[N, K']^T  (both bf16 K-major)
// CTA 128x128, BK = 64 bf16 (128 B swizzled rows), 4-stage cp.async.
// 256 threads = 8 warps in 2(m) x 4(n); warp tile 64x32 (4x4 m16n8k16).
// grid = (Npad/128, M/128)
// =================================================================
template <int EP>
__global__ __launch_bounds__(256, 1) void tc_gemm(
    const __nv_bfloat16* __restrict__ A, const __nv_bfloat16* __restrict__ Bm,
    float* __restrict__ C, const float* __restrict__ bias,
    int N, int KT, int Ktot)
{
    constexpr int NS  = 4;
    constexpr int AB  = 128 * 128;       // 16 KB per A tile
    constexpr int STG = 2 * AB;          // 32 KB per stage

    extern __shared__ char smem[];
    const uint32_t sb = s2u(smem);
    const int tid  = threadIdx.x;
    const int wid  = tid >> 5;
    const int lane = tid & 31;
    const int bm   = blockIdx.y * 128;
    const int bn   = blockIdx.x * 128;
    const int wm64 = (wid >> 2) * 64;    // warp m-offset (0 / 64)
    const int wn32 = (wid & 3) * 32;     // warp n-offset (0/32/64/96)

    // ---- cp.async chunk assignments (16 B chunks, XOR-swizzled dst) ----
    uint32_t aoff[4]; const char* asrc[4];
    uint32_t boff[4]; const char* bsrc[4];
#pragma unroll
    for (int j = 0; j < 4; j++) {
        int ch = tid + j * 256, r = ch >> 3, c = ch & 7;
        uint32_t sw = (uint32_t)(r * 128 + ((c ^ (r & 7)) << 4));
        aoff[j] = sw;
        boff[j] = (uint32_t)AB + sw;
        asrc[j] = (const char*)(A + (size_t)(bm + r) * Ktot + c * 8);
        bsrc[j] = (const char*)(Bm + (size_t)(bn + r) * Ktot + c * 8);
    }

    auto fill = [&](int s, int kt) {
        if (kt < KT) {
            size_t adv = (size_t)kt * 128;       // 64 bf16 = 128 B per k-tile
            uint32_t st = sb + (uint32_t)(s * STG);
#pragma unroll
            for (int j = 0; j < 4; j++) cp16(st + aoff[j], asrc[j] + adv);
#pragma unroll
            for (int j = 0; j < 4; j++) cp16(st + boff[j], bsrc[j] + adv);
        }
        cp_commit();
    };

#pragma unroll
    for (int p = 0; p < NS - 1; p++) fill(p, p);

    float acc[4][4][4];
#pragma unroll
    for (int i = 0; i < 4; i++)
#pragma unroll
        for (int j = 0; j < 4; j++)
#pragma unroll
            for (int q = 0; q < 4; q++) acc[i][j][q] = 0.f;

    const int ll = lane & 15;       // ldmatrix row within 16
    const int ch = lane >> 4;       // ldmatrix k-chunk select (0/1)

    for (int it = 0; it < KT; it++) {
        const int s = it & (NS - 1);
        cp_wait<NS - 2>();
        __syncthreads();
        fill((it + NS - 1) & (NS - 1), it + NS - 1);

        const uint32_t sA = sb + (uint32_t)(s * STG);
        const uint32_t sB = sA + (uint32_t)AB;

#pragma unroll
        for (int kk = 0; kk < 4; kk++) {
            const int kc = 2 * kk + ch;          // 16B chunk index for this lane
            uint32_t a[4][4], bf[2][4];
#pragma unroll
            for (int i = 0; i < 4; i++) {
                int r = wm64 + i * 16 + ll;
                LDSM4(a[i][0], a[i][1], a[i][2], a[i][3],
                      sA + (uint32_t)(r * 128 + ((kc ^ (r & 7)) << 4)));
            }
#pragma unroll
            for (int j16 = 0; j16 < 2; j16++) {
                int r = wn32 + j16 * 16 + ll;
                LDSM4(bf[j16][0], bf[j16][1], bf[j16][2], bf[j16][3],
                      sB + (uint32_t)(r * 128 + ((kc ^ (r & 7)) << 4)));
            }
#pragma unroll
            for (int i = 0; i < 4; i++)
#pragma unroll
                for (int j = 0; j < 4; j++) {
                    const int j16 = j >> 1, jo = j & 1;
                    mma_bf16(acc[i][j][0], acc[i][j][1], acc[i][j][2], acc[i][j][3],
                             a[i][0], a[i][1], a[i][2], a[i][3],
                             bf[j16][jo], bf[j16][jo + 2]);
                }
        }
    }

    // ---- epilogue: registers -> global ----
    const int er = bm + wm64 + (lane >> 2);
    const int ec = bn + wn32 + (lane & 3) * 2;
#pragma unroll
    for (int i = 0; i < 4; i++) {
#pragma unroll
        for (int j = 0; j < 4; j++) {
            int row = er + i * 16;
            int col = ec + j * 8;
            if (col < N) {
                float2 v0, v1;
                v0.x = epilogue_op<EP>(acc[i][j][0], bias, col);
                v0.y = epilogue_op<EP>(acc[i][j][1], bias, col + 1);
                v1.x = epilogue_op<EP>(acc[i][j][2], bias, col);
                v1.y = epilogue_op<EP>(acc[i][j][3], bias, col + 1);
                *(float2*)(C + (size_t)row * N + col)       = v0;
                *(float2*)(C + (size_t)(row + 8) * N + col) = v1;
            }
        }
    }
}

// =================================================================
// Pack A: fp32 [M, K (lda)] -> bf16 [M, 3*Kseg] as [hi | lo | hi]
// =================================================================
__global__ void pack_a_kernel(const float* __restrict__ A, __nv_bfloat16* __restrict__ out,
                              int M, int K, int Kseg, int lda)
{
    size_t idx = (size_t)blockIdx.x * blockDim.x + threadIdx.x;
    size_t tot = (size_t)M * Kseg;
    if (idx >= tot) return;
    int kk   = (int)(idx % Kseg);
    size_t m = idx / Kseg;
    float v = (kk < K) ? A[m * lda + kk] : 0.f;
    __nv_bfloat16 hi = __float2bfloat16(v);
    __nv_bfloat16 lo = __float2bfloat16(v - __bfloat162float(hi));
    __nv_bfloat16* o = out + m * (size_t)(3 * Kseg);
    o[kk]            = hi;
    o[Kseg + kk]     = lo;
    o[2 * Kseg + kk] = hi;
}

// =================================================================
// Pack B (transpose): fp32 [K, N] -> bf16 [Npad, 3*Kseg] rows = [hi | hi | lo]
// =================================================================
__global__ void pack_b_kernel(const float* __restrict__ B, __nv_bfloat16* __restrict__ out,
                              int K, int N, int Kseg, int Npad)
{
    __shared__ float s[32][33];
    const int kt = blockIdx.y * 32, nt = blockIdx.x * 32;
    const int tx = threadIdx.x, ty = threadIdx.y;
    const int k = kt + ty, n = nt + tx;
    s[ty][tx] = (k < K && n < N) ? B[(size_t)k * N + n] : 0.f;
    __syncthreads();
    const int on = nt + ty, ok = kt + tx;
    if (on < Npad && ok < Kseg) {
        float v = s[tx][ty];
        __nv_bfloat16 hi = __float2bfloat16(v);
        __nv_bfloat16 lo = __float2bfloat16(v - __bfloat162float(hi));
        __nv_bfloat16* o = out + (size_t)on * (3 * Kseg);
        o[ok]            = hi;
        o[Kseg + ok]     = hi;
        o[2 * Kseg + ok] = lo;
    }
}

// =================================================================
// Depthwise causal conv (width 4) + bias + SiLU
// =================================================================
__global__ __launch_bounds__(256) void conv_silu_kernel(
    const float* __restrict__ cw, const float* __restrict__ cb)
{
    const int d  = blockIdx.x * 256 + threadIdx.x;
    const int b  = blockIdx.z;
    const int l0 = blockIdx.y * 64;

    const float w0 = cw[d * 4 + 0], w1 = cw[d * 4 + 1];
    const float w2 = cw[d * 4 + 2], w3 = cw[d * 4 + 3];
    const float bi = cb[d];

    const float* xp = g_xz + ((size_t)(b * L_SEQ + l0)) * (2 * DINNER) + d;
    float*       op = g_xc + ((size_t)(b * L_SEQ + l0)) * DINNER + d;

    float xm3, xm2, xm1;
    if (l0 == 0) {
        xm3 = xm2 = xm1 = 0.f;
    } else {
        xm3 = xp[-(ptrdiff_t)3 * 2 * DINNER];
        xm2 = xp[-(ptrdiff_t)2 * 2 * DINNER];
        xm1 = xp[-(ptrdiff_t)1 * 2 * DINNER];
    }
#pragma unroll 4
    for (int i = 0; i < 64; i++) {
        float x0 = xp[0];
        float v  = fmaf(w0, xm3, fmaf(w1, xm2, fmaf(w2, xm1, fmaf(w3, x0, bi))));
        *op = v / (1.f + __expf(-v));
        xm3 = xm2; xm2 = xm1; xm1 = x0;
        xp += 2 * DINNER; op += DINNER;
    }
}

// =================================================================
// Selective scan + skip + z-gating
// =================================================================
__global__ __launch_bounds__(256) void scan_kernel(
    const float* __restrict__ A_log, const float* __restrict__ Dp)
{
    const int wid  = blockIdx.x * 8 + (threadIdx.x >> 5);
    const int lane = threadIdx.x & 31;
    const int b    = wid / (DINNER / 2);
    const int dpr  = wid % (DINNER / 2);
    const int half = lane >> 4;
    const int n    = lane & 15;
    const int d    = dpr * 2 + half;

    const float A  = -__expf(A_log[d * D_STATE + n]);
    const float Dd = Dp[d];

    const size_t base = (size_t)b * L_SEQ;
    const float* dp = g_delta + base * DINNER + d;
    const float* up = g_xc    + base * DINNER + d;
    const float* bp = g_xdbl  + base * XDBL_N + DT_RANK + n;
    const float* cp = g_xdbl  + base * XDBL_N + DT_RANK + D_STATE + n;
    const float* zp = g_xz    + base * (2 * DINNER) + DINNER + d;
    float*       yp = g_y     + base * DINNER + d;

    float pd[4], pu[4], pb[4], pc[4];
#pragma unroll
    for (int g = 0; g < 4; g++) {
        pd[g] = __ldg(dp + g * DINNER);
        pu[g] = __ldg(up + g * DINNER);
        pb[g] = __ldg(bp + g * XDBL_N);
        pc[g] = __ldg(cp + g * XDBL_N);
    }

    float h = 0.f;
    for (int t0 = 0; t0 < L_SEQ; t0 += 4) {
        float cd[4], cu[4], cb_[4], cc[4];
#pragma unroll
        for (int g = 0; g < 4; g++) { cd[g]=pd[g]; cu[g]=pu[g]; cb_[g]=pb[g]; cc[g]=pc[g]; }

        dp += 4 * DINNER; up += 4 * DINNER; bp += 4 * XDBL_N; cp += 4 * XDBL_N;
        if (t0 + 4 < L_SEQ) {
#pragma unroll
            for (int g = 0; g < 4; g++) {
                pd[g] = __ldg(dp + g * DINNER);
                pu[g] = __ldg(up + g * DINNER);
                pb[g] = __ldg(bp + g * XDBL_N);
                pc[g] = __ldg(cp + g * XDBL_N);
            }
        }

#pragma unroll
        for (int g = 0; g < 4; g++) {
            float dt = cd[g], u = cu[g];
            float dA = __expf(dt * A);
            h = fmaf(dA, h, dt * u * cb_[g]);
            float p = h * cc[g];
            p += __shfl_xor_sync(0xffffffffu, p, 1);
            p += __shfl_xor_sync(0xffffffffu, p, 2);
            p += __shfl_xor_sync(0xffffffffu, p, 4);
            p += __shfl_xor_sync(0xffffffffu, p, 8);
            if (n == 0) {
                float z  = __ldg(zp + g * (2 * DINNER));
                float sz = z / (1.f + __expf(-z));
                yp[(size_t)g * DINNER] = (p + u * Dd) * sz;
            }
        }
        zp += (size_t)4 * 2 * DINNER; yp += (size_t)4 * DINNER;
    }
}

// =================================================================
extern "C" void kernel_launch(void* const* d_in, const int* in_sizes, int n_in,
                              void* d_out, int out_size)
{
    const float* hidden = (const float*)d_in[0];
    const float* Win    = (const float*)d_in[1];
    const float* conv_w = (const float*)d_in[2];
    const float* conv_b = (const float*)d_in[3];
    const float* Wx     = (const float*)d_in[4];
    const float* Wdt    = (const float*)d_in[5];
    const float* bdt    = (const float*)d_in[6];
    const float* A_log  = (const float*)d_in[7];
    const float* Dp     = (const float*)d_in[8];
    const float* Wout   = (const float*)d_in[9];
    float* out = (float*)d_out;

    float *xz, *xc, *xdbl, *delta, *y;
    __nv_bfloat16 *Ain, *Bin, *Au, *Bx, *Adt, *Bdt, *Ay, *Bout;
    cudaGetSymbolAddress((void**)&xz,    g_xz);
    cudaGetSymbolAddress((void**)&xc,    g_xc);
    cudaGetSymbolAddress((void**)&xdbl,  g_xdbl);
    cudaGetSymbolAddress((void**)&delta, g_delta);
    cudaGetSymbolAddress((void**)&y,     g_y);
    cudaGetSymbolAddress((void**)&Ain,   g_Ain);
    cudaGetSymbolAddress((void**)&Bin,   g_Bin);
    cudaGetSymbolAddress((void**)&Au,    g_Au);
    cudaGetSymbolAddress((void**)&Bx,    g_Bx);
    cudaGetSymbolAddress((void**)&Adt,   g_Adt);
    cudaGetSymbolAddress((void**)&Bdt,   g_Bdt);
    cudaGetSymbolAddress((void**)&Ay,    g_Ay);
    cudaGetSymbolAddress((void**)&Bout,  g_Bout);

    const int SMEM = 4 * 2 * 128 * 128;   // 131072
    cudaFuncSetAttribute(tc_gemm<0>, cudaFuncAttributeMaxDynamicSharedMemorySize, SMEM);
    cudaFuncSetAttribute(tc_gemm<1>, cudaFuncAttributeMaxDynamicSharedMemorySize, SMEM);

    // 1) in-proj: xz = hidden @ Win   [8192,768]x[768,3072], K'=2304
    {
        size_t tot = (size_t)NROWS * DMODEL;
        pack_a_kernel<<<(unsigned)((tot + 255) / 256), 256>>>(hidden, Ain, NROWS, DMODEL, DMODEL, DMODEL);
        pack_b_kernel<<<dim3(2*DINNER/32, DMODEL/32), dim3(32,32)>>>(Win, Bin, DMODEL, 2*DINNER, DMODEL, 2*DINNER);
        tc_gemm<0><<<dim3(2*DINNER/128, NROWS/128), 256, SMEM>>>(
            Ain, Bin, xz, nullptr, 2*DINNER, 3*DMODEL/64, 3*DMODEL);
    }

    // 2) conv + silu -> u
    conv_silu_kernel<<<dim3(DINNER/256, L_SEQ/64, B_SZ), 256>>>(conv_w, conv_b);

    // 3) x_dbl = u @ Wx   [8192,1536]x[1536,80], K'=4608, Npad=128
    {
        size_t tot = (size_t)NROWS * DINNER;
        pack_a_kernel<<<(unsigned)((tot + 255) / 256), 256>>>(xc, Au, NROWS, DINNER, DINNER, DINNER);
        pack_b_kernel<<<dim3(128/32, DINNER/32), dim3(32,32)>>>(Wx, Bx, DINNER, XDBL_N, DINNER, 128);
        tc_gemm<0><<<dim3(1, NROWS/128), 256, SMEM>>>(
            Au, Bx, xdbl, nullptr, XDBL_N, 3*DINNER/64, 3*DINNER);
    }

    // 4) delta = softplus(x_dbl[:, :48] @ Wdt + bdt)   K=48 -> Kseg=64, K'=192
    {
        size_t tot = (size_t)NROWS * 64;
        pack_a_kernel<<<(unsigned)((tot + 255) / 256), 256>>>(xdbl, Adt, NROWS, DT_RANK, 64, XDBL_N);
        pack_b_kernel<<<dim3(DINNER/32, 64/32), dim3(32,32)>>>(Wdt, Bdt, DT_RANK, DINNER, 64, DINNER);
        tc_gemm<1><<<dim3(DINNER/128, NROWS/128), 256, SMEM>>>(
            Adt, Bdt, delta, bdt, DINNER, 3, 192);
    }

    // 5) selective scan + skip + gating -> y
    scan_kernel<<<B_SZ * (DINNER/2) / 8, 256>>>(A_log, Dp);

    // 6) out-proj: out = y @ Wout   [8192,1536]x[1536,768], K'=4608
    {
        size_t tot = (size_t)NROWS * DINNER;
        pack_a_kernel<<<(unsigned)((tot + 255) / 256), 256>>>(y, Ay, NROWS, DINNER, DINNER, DINNER);
        pack_b_kernel<<<dim3(DMODEL/32, DINNER/32), dim3(32,32)>>>(Wout, Bout, DINNER, DMODEL, DINNER, DMODEL);
        tc_gemm<0><<<dim3(DMODEL/128, NROWS/128), 256, SMEM>>>(
            Ay, Bout, out, nullptr, DMODEL, 3*DINNER/64, 3*DINNER);
    }
}

// round 4
// speedup vs baseline: 1.2728x; 1.0265x over previous
#include <cuda_runtime.h>
#include <cuda_bf16.h>
#include <math.h>
#include <stdint.h>

#define B_SZ    2
#define L_SEQ   4096
#define DMODEL  768
#define DINNER  1536
#define DT_RANK 48
#define D_STATE 16
#define NROWS   (B_SZ * L_SEQ)          /* 8192 */
#define XDBL_N  (DT_RANK + 2 * D_STATE) /* 80   */

// ---------------- fp32 scratch ----------------
__device__ __align__(16) float g_xz[(size_t)NROWS * 2 * DINNER];
__device__ __align__(16) float g_xc[(size_t)NROWS * DINNER];
__device__ __align__(16) float g_xdbl[(size_t)NROWS * XDBL_N];
__device__ __align__(16) float g_delta[(size_t)NROWS * DINNER];

// ---------------- bf16 3-term packed operands ----------------
// A' = [A_hi | A_lo | A_hi] along K ; B' (transposed, [N,K'] K-major) = [B_hi | B_hi | B_lo]
__device__ __align__(128) __nv_bfloat16 g_Ain [(size_t)NROWS * 3 * DMODEL];
__device__ __align__(128) __nv_bfloat16 g_Bin [(size_t)(2*DINNER) * 3 * DMODEL];
__device__ __align__(128) __nv_bfloat16 g_Au  [(size_t)NROWS * 3 * DINNER];
__device__ __align__(128) __nv_bfloat16 g_Bx  [(size_t)128 * 3 * DINNER];
__device__ __align__(128) __nv_bfloat16 g_Adt [(size_t)NROWS * 3 * 64];     // pad 48->64, pad stays 0
__device__ __align__(128) __nv_bfloat16 g_Bdt [(size_t)DINNER * 3 * 64];
__device__ __align__(128) __nv_bfloat16 g_Ay  [(size_t)NROWS * 3 * DINNER];
__device__ __align__(128) __nv_bfloat16 g_Bout[(size_t)DMODEL * 3 * DINNER];

// =================================================================
// PTX helpers (base ISA only)
// =================================================================
static __device__ __forceinline__ uint32_t s2u(const void* p) {
    uint32_t a;
    asm("{ .reg .u64 t; cvta.to.shared.u64 t, %1; cvt.u32.u64 %0, t; }"
        : "=r"(a) : "l"(p));
    return a;
}
static __device__ __forceinline__ void cp16(uint32_t d, const void* s) {
    asm volatile("cp.async.cg.shared.global [%0], [%1], 16;" :: "r"(d), "l"(s));
}
static __device__ __forceinline__ void cp_commit() {
    asm volatile("cp.async.commit_group;" ::: "memory");
}
template <int N> static __device__ __forceinline__ void cp_wait() {
    asm volatile("cp.async.wait_group %0;" :: "n"(N) : "memory");
}
#define LDSM4(r0, r1, r2, r3, addr) \
    asm volatile("ldmatrix.sync.aligned.m8n8.x4.shared.b16 {%0,%1,%2,%3}, [%4];" \
                 : "=r"(r0), "=r"(r1), "=r"(r2), "=r"(r3) : "r"(addr))

static __device__ __forceinline__ void mma_bf16(
    float& d0, float& d1, float& d2, float& d3,
    uint32_t a0, uint32_t a1, uint32_t a2, uint32_t a3,
    uint32_t b0, uint32_t b1)
{
    asm volatile(
        "mma.sync.aligned.m16n8k16.row.col.f32.bf16.bf16.f32 "
        "{%0,%1,%2,%3}, {%4,%5,%6,%7}, {%8,%9}, {%0,%1,%2,%3};"
        : "+f"(d0), "+f"(d1), "+f"(d2), "+f"(d3)
        : "r"(a0), "r"(a1), "r"(a2), "r"(a3), "r"(b0), "r"(b1));
}

static __device__ __forceinline__ void split_bf16(float v, __nv_bfloat16& hi, __nv_bfloat16& lo) {
    hi = __float2bfloat16(v);
    lo = __float2bfloat16(v - __bfloat162float(hi));
}

// =================================================================
// HMMA GEMM: C[M,N] = A'[M,K'] * B'[N,K']^T (both bf16, K-major)
// 512 threads = 16 warps (4m x 4n), CTA tile 128 x BN, warp tile 32 x BN/4,
// BK=64 bf16 (128B swizzled rows), NS=3 cp.async stages.
// EP: 0 plain fp32, 1 softplus(+bias), 2 xdbl (fp32 cols<80 + packed Adt cols<48)
// =================================================================
template <int BN, int EP>
__global__ __launch_bounds__(512, 1) void tc_gemm(
    const __nv_bfloat16* __restrict__ A, const __nv_bfloat16* __restrict__ Bm,
    float* __restrict__ C, const float* __restrict__ bias,
    int N, int KT, int Ktot)
{
    constexpr int NS  = 3;
    constexpr int AB  = 128 * 128;          // 16 KB
    constexpr int BB  = BN * 128;
    constexpr int STG = AB + BB;
    constexpr int WN  = BN / 4;             // warp n extent (64 or 32)
    constexpr int NB  = WN / 16;            // B LDSM4 groups per kk (4 or 2)
    constexpr int NJ  = WN / 8;             // n8 blocks per warp (8 or 4)
    constexpr int ACH = 2;                  // A chunks per thread
    constexpr int BCH = BN / 64;            // B chunks per thread

    extern __shared__ char smem[];
    const uint32_t sb = s2u(smem);
    const int tid  = threadIdx.x;
    const int wid  = tid >> 5;
    const int lane = tid & 31;
    const int bm   = blockIdx.y * 128;
    const int bn   = blockIdx.x * BN;
    const int wm   = (wid & 3) * 32;
    const int wn   = (wid >> 2) * WN;

    // ---- cp.async chunk assignments ----
    uint32_t aoff[ACH]; const char* asrc[ACH];
#pragma unroll
    for (int j = 0; j < ACH; j++) {
        int ch = tid + j * 512, r = ch >> 3, c = ch & 7;
        aoff[j] = (uint32_t)(r * 128 + ((c ^ (r & 7)) << 4));
        asrc[j] = (const char*)(A + (size_t)(bm + r) * Ktot + c * 8);
    }
    uint32_t boff[BCH]; const char* bsrc[BCH];
#pragma unroll
    for (int j = 0; j < BCH; j++) {
        int ch = tid + j * 512, r = ch >> 3, c = ch & 7;
        boff[j] = (uint32_t)AB + (uint32_t)(r * 128 + ((c ^ (r & 7)) << 4));
        bsrc[j] = (const char*)(Bm + (size_t)(bn + r) * Ktot + c * 8);
    }

    auto fill = [&](int s, int kt) {
        if (kt < KT) {
            size_t adv = (size_t)kt * 128;
            uint32_t st = sb + (uint32_t)(s * STG);
#pragma unroll
            for (int j = 0; j < ACH; j++) cp16(st + aoff[j], asrc[j] + adv);
#pragma unroll
            for (int j = 0; j < BCH; j++) cp16(st + boff[j], bsrc[j] + adv);
        }
        cp_commit();
    };

    // ---- ldmatrix address precompute ----
    const int ll = lane & 15;
    const int cs = lane >> 4;     // k-chunk select within kk
    uint32_t aBase[2]; int aSwz[2];
#pragma unroll
    for (int i = 0; i < 2; i++) {
        int r = wm + i * 16 + ll;
        aBase[i] = (uint32_t)(r * 128);
        aSwz[i]  = r & 7;
    }
    uint32_t bBase[NB]; int bSwz[NB];
#pragma unroll
    for (int g = 0; g < NB; g++) {
        int r = wn + g * 16 + ll;
        bBase[g] = (uint32_t)AB + (uint32_t)(r * 128);
        bSwz[g]  = r & 7;
    }

    fill(0, 0);
    fill(1, 1);

    float acc[2][NJ][4];
#pragma unroll
    for (int i = 0; i < 2; i++)
#pragma unroll
        for (int j = 0; j < NJ; j++)
#pragma unroll
            for (int q = 0; q < 4; q++) acc[i][j][q] = 0.f;

    int s = 0, fs = 2;
    for (int it = 0; it < KT; it++) {
        cp_wait<NS - 2>();
        __syncthreads();
        fill(fs, it + NS - 1);

        const uint32_t st = sb + (uint32_t)(s * STG);
#pragma unroll
        for (int kk = 0; kk < 4; kk++) {
            const int kc = 2 * kk + cs;
            uint32_t a[2][4], bf[NB][4];
#pragma unroll
            for (int i = 0; i < 2; i++)
                LDSM4(a[i][0], a[i][1], a[i][2], a[i][3],
                      st + aBase[i] + (uint32_t)((kc ^ aSwz[i]) << 4));
#pragma unroll
            for (int g = 0; g < NB; g++)
                LDSM4(bf[g][0], bf[g][1], bf[g][2], bf[g][3],
                      st + bBase[g] + (uint32_t)((kc ^ bSwz[g]) << 4));
#pragma unroll
            for (int i = 0; i < 2; i++)
#pragma unroll
                for (int j = 0; j < NJ; j++) {
                    const int g = j >> 1, jo = j & 1;
                    mma_bf16(acc[i][j][0], acc[i][j][1], acc[i][j][2], acc[i][j][3],
                             a[i][0], a[i][1], a[i][2], a[i][3],
                             bf[g][jo], bf[g][jo + 2]);
                }
        }
        s  = (s  == NS - 1) ? 0 : s  + 1;
        fs = (fs == NS - 1) ? 0 : fs + 1;
    }
    cp_wait<0>();

    // ---- epilogue ----
    const int er = bm + wm + (lane >> 2);
    const int ec = bn + wn + (lane & 3) * 2;
#pragma unroll
    for (int i = 0; i < 2; i++) {
#pragma unroll
        for (int j = 0; j < NJ; j++) {
            const int row = er + i * 16;
            const int col = ec + j * 8;
            if (EP == 0) {
                float2 v0 = { acc[i][j][0], acc[i][j][1] };
                float2 v1 = { acc[i][j][2], acc[i][j][3] };
                *(float2*)(C + (size_t)row * N + col)       = v0;
                *(float2*)(C + (size_t)(row + 8) * N + col) = v1;
            } else if (EP == 1) {
                float t0 = acc[i][j][0] + bias[col];
                float t1 = acc[i][j][1] + bias[col + 1];
                float t2 = acc[i][j][2] + bias[col];
                float t3 = acc[i][j][3] + bias[col + 1];
                t0 = (t0 > 20.f) ? t0 : log1pf(expf(t0));
                t1 = (t1 > 20.f) ? t1 : log1pf(expf(t1));
                t2 = (t2 > 20.f) ? t2 : log1pf(expf(t2));
                t3 = (t3 > 20.f) ? t3 : log1pf(expf(t3));
                float2 v0 = { t0, t1 }, v1 = { t2, t3 };
                *(float2*)(C + (size_t)row * N + col)       = v0;
                *(float2*)(C + (size_t)(row + 8) * N + col) = v1;
            } else {  // EP == 2: xdbl
#pragma unroll
                for (int q = 0; q < 2; q++) {
                    const int r = row + q * 8;
                    float e0 = acc[i][j][2 * q], e1 = acc[i][j][2 * q + 1];
                    if (col < XDBL_N) {
                        float2 v = { e0, e1 };
                        *(float2*)(g_xdbl + (size_t)r * XDBL_N + col) = v;
                    }
                    if (col < DT_RANK) {
                        __nv_bfloat16 h0, l0, h1, l1;
                        split_bf16(e0, h0, l0);
                        split_bf16(e1, h1, l1);
                        __nv_bfloat16* o = g_Adt + (size_t)r * 192;
                        o[col]       = h0; o[col + 1]       = h1;
                        o[64 + col]  = l0; o[64 + col + 1]  = l1;
                        o[128 + col] = h0; o[128 + col + 1] = h1;
                    }
                }
            }
        }
    }
}

// =================================================================
// Pack A (hidden only): fp32 [M,K] -> bf16 [M, 3K] as [hi | lo | hi]
// =================================================================
__global__ void pack_a_kernel(const float* __restrict__ A, __nv_bfloat16* __restrict__ out,
                              int M, int K, int Kseg, int lda)
{
    size_t idx = (size_t)blockIdx.x * blockDim.x + threadIdx.x;
    size_t tot = (size_t)M * Kseg;
    if (idx >= tot) return;
    int kk   = (int)(idx % Kseg);
    size_t m = idx / Kseg;
    float v = (kk < K) ? A[m * lda + kk] : 0.f;
    __nv_bfloat16 hi, lo;
    split_bf16(v, hi, lo);
    __nv_bfloat16* o = out + m * (size_t)(3 * Kseg);
    o[kk]            = hi;
    o[Kseg + kk]     = lo;
    o[2 * Kseg + kk] = hi;
}

// =================================================================
// Pack B (transpose): fp32 [K,N] -> bf16 [Npad, 3*Kseg] rows = [hi | hi | lo]
// =================================================================
__global__ void pack_b_kernel(const float* __restrict__ B, __nv_bfloat16* __restrict__ out,
                              int K, int N, int Kseg, int Npad)
{
    __shared__ float s[32][33];
    const int kt = blockIdx.y * 32, nt = blockIdx.x * 32;
    const int tx = threadIdx.x, ty = threadIdx.y;
    const int k = kt + ty, n = nt + tx;
    s[ty][tx] = (k < K && n < N) ? B[(size_t)k * N + n] : 0.f;
    __syncthreads();
    const int on = nt + ty, ok = kt + tx;
    if (on < Npad && ok < Kseg) {
        float v = s[tx][ty];
        __nv_bfloat16 hi, lo;
        split_bf16(v, hi, lo);
        __nv_bfloat16* o = out + (size_t)on * (3 * Kseg);
        o[ok]            = hi;
        o[Kseg + ok]     = hi;
        o[2 * Kseg + ok] = lo;
    }
}

// =================================================================
// Depthwise causal conv (width 4) + bias + SiLU; writes fp32 u AND packed Au
// =================================================================
__global__ __launch_bounds__(256) void conv_silu_kernel(
    const float* __restrict__ cw, const float* __restrict__ cb)
{
    const int d  = blockIdx.x * 256 + threadIdx.x;
    const int b  = blockIdx.z;
    const int l0 = blockIdx.y * 64;

    const float w0 = cw[d * 4 + 0], w1 = cw[d * 4 + 1];
    const float w2 = cw[d * 4 + 2], w3 = cw[d * 4 + 3];
    const float bi = cb[d];

    const size_t row0 = (size_t)(b * L_SEQ + l0);
    const float* xp = g_xz + row0 * (2 * DINNER) + d;
    float*       op = g_xc + row0 * DINNER + d;
    __nv_bfloat16* ap = g_Au + row0 * (3 * DINNER) + d;

    float xm3, xm2, xm1;
    if (l0 == 0) {
        xm3 = xm2 = xm1 = 0.f;
    } else {
        xm3 = xp[-(ptrdiff_t)3 * 2 * DINNER];
        xm2 = xp[-(ptrdiff_t)2 * 2 * DINNER];
        xm1 = xp[-(ptrdiff_t)1 * 2 * DINNER];
    }
#pragma unroll 4
    for (int i = 0; i < 64; i++) {
        float x0 = xp[0];
        float v  = fmaf(w0, xm3, fmaf(w1, xm2, fmaf(w2, xm1, fmaf(w3, x0, bi))));
        float u  = v / (1.f + __expf(-v));
        *op = u;
        __nv_bfloat16 hi, lo;
        split_bf16(u, hi, lo);
        ap[0]          = hi;
        ap[DINNER]     = lo;
        ap[2 * DINNER] = hi;
        xm3 = xm2; xm2 = xm1; xm1 = x0;
        xp += 2 * DINNER; op += DINNER; ap += 3 * DINNER;
    }
}

// =================================================================
// Selective scan + skip + z-gating; writes packed Ay directly
// =================================================================
__global__ __launch_bounds__(256) void scan_kernel(
    const float* __restrict__ A_log, const float* __restrict__ Dp)
{
    const int wid  = blockIdx.x * 8 + (threadIdx.x >> 5);
    const int lane = threadIdx.x & 31;
    const int b    = wid / (DINNER / 2);
    const int dpr  = wid % (DINNER / 2);
    const int half = lane >> 4;
    const int n    = lane & 15;
    const int d    = dpr * 2 + half;

    const float A  = -__expf(A_log[d * D_STATE + n]);
    const float Dd = Dp[d];

    const size_t base = (size_t)b * L_SEQ;
    const float* dp = g_delta + base * DINNER + d;
    const float* up = g_xc    + base * DINNER + d;
    const float* bp = g_xdbl  + base * XDBL_N + DT_RANK + n;
    const float* cp = g_xdbl  + base * XDBL_N + DT_RANK + D_STATE + n;
    const float* zp = g_xz    + base * (2 * DINNER) + DINNER + d;
    __nv_bfloat16* ayp = g_Ay + base * (3 * DINNER) + d;

    float pd[4], pu[4], pb[4], pc[4];
#pragma unroll
    for (int g = 0; g < 4; g++) {
        pd[g] = __ldg(dp + g * DINNER);
        pu[g] = __ldg(up + g * DINNER);
        pb[g] = __ldg(bp + g * XDBL_N);
        pc[g] = __ldg(cp + g * XDBL_N);
    }

    float h = 0.f;
    for (int t0 = 0; t0 < L_SEQ; t0 += 4) {
        float cd[4], cu[4], cb_[4], cc[4];
#pragma unroll
        for (int g = 0; g < 4; g++) { cd[g]=pd[g]; cu[g]=pu[g]; cb_[g]=pb[g]; cc[g]=pc[g]; }

        dp += 4 * DINNER; up += 4 * DINNER; bp += 4 * XDBL_N; cp += 4 * XDBL_N;
        if (t0 + 4 < L_SEQ) {
#pragma unroll
            for (int g = 0; g < 4; g++) {
                pd[g] = __ldg(dp + g * DINNER);
                pu[g] = __ldg(up + g * DINNER);
                pb[g] = __ldg(bp + g * XDBL_N);
                pc[g] = __ldg(cp + g * XDBL_N);
            }
        }

#pragma unroll
        for (int g = 0; g < 4; g++) {
            float dt = cd[g], u = cu[g];
            float dA = __expf(dt * A);
            h = fmaf(dA, h, dt * u * cb_[g]);
            float p = h * cc[g];
            p += __shfl_xor_sync(0xffffffffu, p, 1);
            p += __shfl_xor_sync(0xffffffffu, p, 2);
            p += __shfl_xor_sync(0xffffffffu, p, 4);
            p += __shfl_xor_sync(0xffffffffu, p, 8);
            if (n == 0) {
                float z  = __ldg(zp + g * (2 * DINNER));
                float sz = z / (1.f + __expf(-z));
                float yv = (p + u * Dd) * sz;
                __nv_bfloat16 hi, lo;
                split_bf16(yv, hi, lo);
                __nv_bfloat16* o = ayp + (size_t)g * (3 * DINNER);
                o[0]          = hi;
                o[DINNER]     = lo;
                o[2 * DINNER] = hi;
            }
        }
        zp += (size_t)4 * 2 * DINNER; ayp += (size_t)4 * 3 * DINNER;
    }
}

// =================================================================
extern "C" void kernel_launch(void* const* d_in, const int* in_sizes, int n_in,
                              void* d_out, int out_size)
{
    const float* hidden = (const float*)d_in[0];
    const float* Win    = (const float*)d_in[1];
    const float* conv_w = (const float*)d_in[2];
    const float* conv_b = (const float*)d_in[3];
    const float* Wx     = (const float*)d_in[4];
    const float* Wdt    = (const float*)d_in[5];
    const float* bdt    = (const float*)d_in[6];
    const float* A_log  = (const float*)d_in[7];
    const float* Dp     = (const float*)d_in[8];
    const float* Wout   = (const float*)d_in[9];
    float* out = (float*)d_out;

    float *xz, *delta;
    __nv_bfloat16 *Ain, *Bin, *Au, *Bx, *Adt, *Bdt, *Ay, *Bout;
    cudaGetSymbolAddress((void**)&xz,    g_xz);
    cudaGetSymbolAddress((void**)&delta, g_delta);
    cudaGetSymbolAddress((void**)&Ain,   g_Ain);
    cudaGetSymbolAddress((void**)&Bin,   g_Bin);
    cudaGetSymbolAddress((void**)&Au,    g_Au);
    cudaGetSymbolAddress((void**)&Bx,    g_Bx);
    cudaGetSymbolAddress((void**)&Adt,   g_Adt);
    cudaGetSymbolAddress((void**)&Bdt,   g_Bdt);
    cudaGetSymbolAddress((void**)&Ay,    g_Ay);
    cudaGetSymbolAddress((void**)&Bout,  g_Bout);

    const int SM256 = 3 * (16384 + 256 * 128);   // 147456
    const int SM128 = 3 * (16384 + 128 * 128);   // 98304
    cudaFuncSetAttribute(tc_gemm<256,0>, cudaFuncAttributeMaxDynamicSharedMemorySize, SM256);
    cudaFuncSetAttribute(tc_gemm<256,1>, cudaFuncAttributeMaxDynamicSharedMemorySize, SM256);
    cudaFuncSetAttribute(tc_gemm<128,0>, cudaFuncAttributeMaxDynamicSharedMemorySize, SM128);
    cudaFuncSetAttribute(tc_gemm<128,2>, cudaFuncAttributeMaxDynamicSharedMemorySize, SM128);

    // #1 pack A(hidden)
    {
        size_t tot = (size_t)NROWS * DMODEL;
        pack_a_kernel<<<(unsigned)((tot + 255) / 256), 256>>>(hidden, Ain, NROWS, DMODEL, DMODEL, DMODEL);
    }
    // #2 pack B(Win)
    pack_b_kernel<<<dim3(2*DINNER/32, DMODEL/32), dim3(32,32)>>>(Win, Bin, DMODEL, 2*DINNER, DMODEL, 2*DINNER);
    // #3 pack B(Wdt)  (independent — placed here so the big GEMM lands on launch #4)
    pack_b_kernel<<<dim3(DINNER/32, 64/32), dim3(32,32)>>>(Wdt, Bdt, DT_RANK, DINNER, 64, DINNER);

    // #4 in-proj GEMM: xz = hidden @ Win   [8192,768]x[768,3072], K'=2304
    tc_gemm<256,0><<<dim3(2*DINNER/256, NROWS/128), 512, SM256>>>(
        Ain, Bin, xz, nullptr, 2*DINNER, 3*DMODEL/64, 3*DMODEL);

    // #5 pack B(Wx)
    pack_b_kernel<<<dim3(128/32, DINNER/32), dim3(32,32)>>>(Wx, Bx, DINNER, XDBL_N, DINNER, 128);
    // #6 conv + silu -> u (fp32) + Au (packed)
    conv_silu_kernel<<<dim3(DINNER/256, L_SEQ/64, B_SZ), 256>>>(conv_w, conv_b);
    // #7 x_dbl GEMM: [8192,1536]x[1536,80], K'=4608, Npad=128; epilogue packs Adt
    tc_gemm<128,2><<<dim3(1, NROWS/128), 512, SM128>>>(
        Au, Bx, nullptr, nullptr, XDBL_N, 3*DINNER/64, 3*DINNER);
    // #8 pack B(Wout)
    pack_b_kernel<<<dim3(DMODEL/32, DINNER/32), dim3(32,32)>>>(Wout, Bout, DINNER, DMODEL, DINNER, DMODEL);
    // #9 dt GEMM + softplus: [8192,48(->64)]x[48,1536], K'=192
    tc_gemm<256,1><<<dim3(DINNER/256, NROWS/128), 512, SM256>>>(
        Adt, Bdt, delta, bdt, DINNER, 3, 192);
    // #10 selective scan (+ skip + gate), writes packed Ay
    scan_kernel<<<B_SZ * (DINNER/2) / 8, 256>>>(A_log, Dp);
    // #11 out-proj GEMM: out = y @ Wout   [8192,1536]x[1536,768], K'=4608
    tc_gemm<128,0><<<dim3(DMODEL/128, NROWS/128), 512, SM128>>>(
        Ay, Bout, out, nullptr, DMODEL, 3*DINNER/64, 3*DINNER);
}

// round 5
// speedup vs baseline: 3.6265x; 2.8492x over previous
#include <cuda_runtime.h>
#include <cuda_bf16.h>
#include <math.h>
#include <stdint.h>

#define B_SZ    2
#define L_SEQ   4096
#define DMODEL  768
#define DINNER  1536
#define DT_RANK 48
#define D_STATE 16
#define NROWS   (B_SZ * L_SEQ)          /* 8192 */
#define XDBL_N  (DT_RANK + 2 * D_STATE) /* 80   */
#define NCHUNK  32
#define CHUNK   128                      /* L_SEQ / NCHUNK */
#define SSTATE  (B_SZ * DINNER * D_STATE)/* 49152 */

// ---------------- fp32 scratch ----------------
__device__ __align__(16) float g_xz[(size_t)NROWS * 2 * DINNER];
__device__ __align__(16) float g_xc[(size_t)NROWS * DINNER];
__device__ __align__(16) float g_xdbl[(size_t)NROWS * XDBL_N];
__device__ __align__(16) float g_delta[(size_t)NROWS * DINNER];
// scan chunk buffers: [chunk][b][d][n]
__device__ __align__(16) float g_P   [(size_t)NCHUNK * SSTATE];
__device__ __align__(16) float g_hloc[(size_t)NCHUNK * SSTATE];
__device__ __align__(16) float g_Hin [(size_t)NCHUNK * SSTATE];

// ---------------- bf16 3-term packed operands ----------------
// A' = [A_hi | A_lo | A_hi] along K ; B' ([N,K'] K-major) = [B_hi | B_hi | B_lo]
__device__ __align__(128) __nv_bfloat16 g_Ain [(size_t)NROWS * 3 * DMODEL];
__device__ __align__(128) __nv_bfloat16 g_Bin [(size_t)(2*DINNER) * 3 * DMODEL];
__device__ __align__(128) __nv_bfloat16 g_Au  [(size_t)NROWS * 3 * DINNER];
__device__ __align__(128) __nv_bfloat16 g_Bx  [(size_t)128 * 3 * DINNER];
__device__ __align__(128) __nv_bfloat16 g_Adt [(size_t)NROWS * 3 * 64];   // pad cols stay 0
__device__ __align__(128) __nv_bfloat16 g_Bdt [(size_t)DINNER * 3 * 64];
__device__ __align__(128) __nv_bfloat16 g_Ay  [(size_t)NROWS * 3 * DINNER];
__device__ __align__(128) __nv_bfloat16 g_Bout[(size_t)DMODEL * 3 * DINNER];

// =================================================================
// PTX helpers
// =================================================================
static __device__ __forceinline__ uint32_t s2u(const void* p) {
    uint32_t a;
    asm("{ .reg .u64 t; cvta.to.shared.u64 t, %1; cvt.u32.u64 %0, t; }"
        : "=r"(a) : "l"(p));
    return a;
}
static __device__ __forceinline__ void cp16(uint32_t d, const void* s) {
    asm volatile("cp.async.cg.shared.global [%0], [%1], 16;" :: "r"(d), "l"(s));
}
static __device__ __forceinline__ void cp_commit() {
    asm volatile("cp.async.commit_group;" ::: "memory");
}
template <int N> static __device__ __forceinline__ void cp_wait() {
    asm volatile("cp.async.wait_group %0;" :: "n"(N) : "memory");
}
#define LDSM4(r0, r1, r2, r3, addr) \
    asm volatile("ldmatrix.sync.aligned.m8n8.x4.shared.b16 {%0,%1,%2,%3}, [%4];" \
                 : "=r"(r0), "=r"(r1), "=r"(r2), "=r"(r3) : "r"(addr))

static __device__ __forceinline__ void mma_bf16(
    float& d0, float& d1, float& d2, float& d3,
    uint32_t a0, uint32_t a1, uint32_t a2, uint32_t a3,
    uint32_t b0, uint32_t b1)
{
    asm volatile(
        "mma.sync.aligned.m16n8k16.row.col.f32.bf16.bf16.f32 "
        "{%0,%1,%2,%3}, {%4,%5,%6,%7}, {%8,%9}, {%0,%1,%2,%3};"
        : "+f"(d0), "+f"(d1), "+f"(d2), "+f"(d3)
        : "r"(a0), "r"(a1), "r"(a2), "r"(a3), "r"(b0), "r"(b1));
}

static __device__ __forceinline__ void split_bf16(float v, __nv_bfloat16& hi, __nv_bfloat16& lo) {
    hi = __float2bfloat16(v);
    lo = __float2bfloat16(v - __bfloat162float(hi));
}
static __device__ __forceinline__ float softplus_f(float t) {
    return (t > 15.f) ? t : __logf(1.f + __expf(t));
}

// =================================================================
// HMMA GEMM: C[M,N] = A'[M,K'] * B'[N,K']^T (bf16 K-major both sides)
// 256 threads = 8 warps (4m x 2n), CTA tile 128x128, warp tile 32x64,
// BK=64 bf16 (128B swizzled rows), NS=3 cp.async stages, 2 CTAs/SM.
// EP: 0 plain, 1 softplus(+bias), 2 xdbl (fp32 cols<80 + packed Adt cols<48)
// =================================================================
template <int EP>
__global__ __launch_bounds__(256, 2) void tc_gemm(
    const __nv_bfloat16* __restrict__ A, const __nv_bfloat16* __restrict__ Bm,
    float* __restrict__ C, const float* __restrict__ bias,
    int N, int KT, int Ktot)
{
    constexpr int NS  = 3;
    constexpr int AB  = 128 * 128;
    constexpr int STG = 2 * AB;

    extern __shared__ char smem[];
    const uint32_t sb = s2u(smem);
    const int tid  = threadIdx.x;
    const int wid  = tid >> 5;
    const int lane = tid & 31;
    const int bm   = blockIdx.y * 128;
    const int bn   = blockIdx.x * 128;
    const int wm   = (wid & 3) * 32;
    const int wn   = (wid >> 2) * 64;

    const size_t rowB = (size_t)Ktot * 2;   // bytes per K'-row

    auto fill = [&](int s, int kt) {
        if (kt < KT) {
            const char* ab = (const char*)A  + (size_t)kt * 128;
            const char* bb = (const char*)Bm + (size_t)kt * 128;
            const uint32_t st = sb + (uint32_t)(s * STG);
#pragma unroll
            for (int j = 0; j < 4; j++) {
                int ch = tid + j * 256, r = ch >> 3, c = ch & 7;
                uint32_t sw = (uint32_t)(r * 128 + ((c ^ (r & 7)) << 4));
                cp16(st + sw,      ab + (size_t)(bm + r) * rowB + c * 16);
                cp16(st + AB + sw, bb + (size_t)(bn + r) * rowB + c * 16);
            }
        }
        cp_commit();
    };

    const int ll = lane & 15;
    const int cs = lane >> 4;

    fill(0, 0);
    fill(1, 1);

    float acc[2][8][4];
#pragma unroll
    for (int i = 0; i < 2; i++)
#pragma unroll
        for (int j = 0; j < 8; j++)
#pragma unroll
            for (int q = 0; q < 4; q++) acc[i][j][q] = 0.f;

    int s = 0, fs = 2;
    for (int it = 0; it < KT; it++) {
        cp_wait<NS - 2>();
        __syncthreads();
        fill(fs, it + NS - 1);

        const uint32_t st = sb + (uint32_t)(s * STG);
#pragma unroll
        for (int kk = 0; kk < 4; kk++) {
            const int kc = 2 * kk + cs;
            uint32_t a[2][4], bf[4][4];
#pragma unroll
            for (int i = 0; i < 2; i++) {
                int r = wm + i * 16 + ll;
                LDSM4(a[i][0], a[i][1], a[i][2], a[i][3],
                      st + (uint32_t)(r * 128 + ((kc ^ (r & 7)) << 4)));
            }
#pragma unroll
            for (int g = 0; g < 4; g++) {
                int r = wn + g * 16 + ll;
                LDSM4(bf[g][0], bf[g][1], bf[g][2], bf[g][3],
                      st + (uint32_t)(AB + r * 128 + ((kc ^ (r & 7)) << 4)));
            }
#pragma unroll
            for (int i = 0; i < 2; i++)
#pragma unroll
                for (int j = 0; j < 8; j++) {
                    const int g = j >> 1, jo = j & 1;
                    mma_bf16(acc[i][j][0], acc[i][j][1], acc[i][j][2], acc[i][j][3],
                             a[i][0], a[i][1], a[i][2], a[i][3],
                             bf[g][jo], bf[g][jo + 2]);
                }
        }
        s  = (s  == NS - 1) ? 0 : s  + 1;
        fs = (fs == NS - 1) ? 0 : fs + 1;
    }
    cp_wait<0>();

    // ---- epilogue ----
    const int er = bm + wm + (lane >> 2);
    const int ec = bn + wn + (lane & 3) * 2;
#pragma unroll
    for (int i = 0; i < 2; i++) {
#pragma unroll
        for (int j = 0; j < 8; j++) {
            const int row = er + i * 16;
            const int col = ec + j * 8;
            if (EP == 0) {
                float2 v0 = { acc[i][j][0], acc[i][j][1] };
                float2 v1 = { acc[i][j][2], acc[i][j][3] };
                *(float2*)(C + (size_t)row * N + col)       = v0;
                *(float2*)(C + (size_t)(row + 8) * N + col) = v1;
            } else if (EP == 1) {
                float2 v0, v1;
                v0.x = softplus_f(acc[i][j][0] + bias[col]);
                v0.y = softplus_f(acc[i][j][1] + bias[col + 1]);
                v1.x = softplus_f(acc[i][j][2] + bias[col]);
                v1.y = softplus_f(acc[i][j][3] + bias[col + 1]);
                *(float2*)(C + (size_t)row * N + col)       = v0;
                *(float2*)(C + (size_t)(row + 8) * N + col) = v1;
            } else {  // EP == 2
#pragma unroll
                for (int q = 0; q < 2; q++) {
                    const int r = row + q * 8;
                    float e0 = acc[i][j][2 * q], e1 = acc[i][j][2 * q + 1];
                    if (col < XDBL_N) {
                        float2 v = { e0, e1 };
                        *(float2*)(g_xdbl + (size_t)r * XDBL_N + col) = v;
                    }
                    if (col < DT_RANK) {
                        __nv_bfloat16 h0, l0, h1, l1;
                        split_bf16(e0, h0, l0);
                        split_bf16(e1, h1, l1);
                        __nv_bfloat16* o = g_Adt + (size_t)r * 192;
                        o[col]       = h0; o[col + 1]       = h1;
                        o[64 + col]  = l0; o[64 + col + 1]  = l1;
                        o[128 + col] = h0; o[128 + col + 1] = h1;
                    }
                }
            }
        }
    }
}

// =================================================================
// Pack A (hidden): fp32 [M,K] -> bf16 [M,3K] = [hi|lo|hi]
// =================================================================
__global__ void pack_a_kernel(const float* __restrict__ A, __nv_bfloat16* __restrict__ out,
                              int M, int K, int Kseg, int lda)
{
    size_t idx = (size_t)blockIdx.x * blockDim.x + threadIdx.x;
    if (idx >= (size_t)M * Kseg) return;
    int kk   = (int)(idx % Kseg);
    size_t m = idx / Kseg;
    float v = (kk < K) ? A[m * lda + kk] : 0.f;
    __nv_bfloat16 hi, lo;
    split_bf16(v, hi, lo);
    __nv_bfloat16* o = out + m * (size_t)(3 * Kseg);
    o[kk]            = hi;
    o[Kseg + kk]     = lo;
    o[2 * Kseg + kk] = hi;
}

// =================================================================
// Pack B (transpose): fp32 [K,N] -> bf16 [Npad, 3*Kseg] = [hi|hi|lo]
// =================================================================
__global__ void pack_b_kernel(const float* __restrict__ B, __nv_bfloat16* __restrict__ out,
                              int K, int N, int Kseg, int Npad)
{
    __shared__ float s[32][33];
    const int kt = blockIdx.y * 32, nt = blockIdx.x * 32;
    const int tx = threadIdx.x, ty = threadIdx.y;
    const int k = kt + ty, n = nt + tx;
    s[ty][tx] = (k < K && n < N) ? B[(size_t)k * N + n] : 0.f;
    __syncthreads();
    const int on = nt + ty, ok = kt + tx;
    if (on < Npad && ok < Kseg) {
        float v = s[tx][ty];
        __nv_bfloat16 hi, lo;
        split_bf16(v, hi, lo);
        __nv_bfloat16* o = out + (size_t)on * (3 * Kseg);
        o[ok]            = hi;
        o[Kseg + ok]     = hi;
        o[2 * Kseg + ok] = lo;
    }
}

// =================================================================
// Depthwise causal conv (w=4) + bias + SiLU -> fp32 u + packed Au
// =================================================================
__global__ __launch_bounds__(256) void conv_silu_kernel(
    const float* __restrict__ cw, const float* __restrict__ cb)
{
    const int d  = blockIdx.x * 256 + threadIdx.x;
    const int b  = blockIdx.z;
    const int l0 = blockIdx.y * 64;

    const float w0 = cw[d * 4 + 0], w1 = cw[d * 4 + 1];
    const float w2 = cw[d * 4 + 2], w3 = cw[d * 4 + 3];
    const float bi = cb[d];

    const size_t row0 = (size_t)(b * L_SEQ + l0);
    const float* xp = g_xz + row0 * (2 * DINNER) + d;
    float*       op = g_xc + row0 * DINNER + d;
    __nv_bfloat16* ap = g_Au + row0 * (3 * DINNER) + d;

    float xm3, xm2, xm1;
    if (l0 == 0) {
        xm3 = xm2 = xm1 = 0.f;
    } else {
        xm3 = xp[-(ptrdiff_t)3 * 2 * DINNER];
        xm2 = xp[-(ptrdiff_t)2 * 2 * DINNER];
        xm1 = xp[-(ptrdiff_t)1 * 2 * DINNER];
    }
#pragma unroll 4
    for (int i = 0; i < 64; i++) {
        float x0 = xp[0];
        float v  = fmaf(w0, xm3, fmaf(w1, xm2, fmaf(w2, xm1, fmaf(w3, x0, bi))));
        float u  = __fdividef(v, 1.f + __expf(-v));
        *op = u;
        __nv_bfloat16 hi, lo;
        split_bf16(u, hi, lo);
        ap[0]          = hi;
        ap[DINNER]     = lo;
        ap[2 * DINNER] = hi;
        xm3 = xm2; xm2 = xm1; xm1 = x0;
        xp += 2 * DINNER; op += DINNER; ap += 3 * DINNER;
    }
}

// =================================================================
// Chunked selective scan.
// Mapping (all passes): warp = (b, channel-pair, chunk); lane = half*16 + n.
// =================================================================
__global__ __launch_bounds__(256) void scan_pass1(const float* __restrict__ A_log)
{
    const int wg   = blockIdx.x * 8 + (threadIdx.x >> 5);
    const int lane = threadIdx.x & 31;
    const int c    = wg & (NCHUNK - 1);
    const int rest = wg >> 5;
    const int b    = rest / (DINNER / 2);
    const int dpr  = rest % (DINNER / 2);
    const int n    = lane & 15;
    const int d    = dpr * 2 + (lane >> 4);

    const float A = -__expf(__ldg(A_log + d * D_STATE + n));

    const size_t row0 = (size_t)b * L_SEQ + (size_t)c * CHUNK;
    const float* dp = g_delta + row0 * DINNER + d;
    const float* up = g_xc    + row0 * DINNER + d;
    const float* bp = g_xdbl  + row0 * XDBL_N + DT_RANK + n;

    float pd[4], pu[4], pb[4];
#pragma unroll
    for (int g = 0; g < 4; g++) {
        pd[g] = __ldg(dp + g * DINNER);
        pu[g] = __ldg(up + g * DINNER);
        pb[g] = __ldg(bp + g * XDBL_N);
    }

    float h = 0.f, sd = 0.f;
    for (int t0 = 0; t0 < CHUNK; t0 += 4) {
        float cd[4], cu[4], cb_[4];
#pragma unroll
        for (int g = 0; g < 4; g++) { cd[g] = pd[g]; cu[g] = pu[g]; cb_[g] = pb[g]; }
        dp += 4 * DINNER; up += 4 * DINNER; bp += 4 * XDBL_N;
        if (t0 + 4 < CHUNK) {
#pragma unroll
            for (int g = 0; g < 4; g++) {
                pd[g] = __ldg(dp + g * DINNER);
                pu[g] = __ldg(up + g * DINNER);
                pb[g] = __ldg(bp + g * XDBL_N);
            }
        }
#pragma unroll
        for (int g = 0; g < 4; g++) {
            float dt = cd[g];
            float dA = __expf(dt * A);
            h  = fmaf(dA, h, dt * cu[g] * cb_[g]);
            sd += dt;
        }
    }
    const size_t o = (size_t)c * SSTATE + ((size_t)b * DINNER + d) * D_STATE + n;
    g_hloc[o] = h;
    g_P[o]    = __expf(A * sd);
}

__global__ void scan_pass2()
{
    const int t = blockIdx.x * 256 + threadIdx.x;   // < SSTATE
    float H = 0.f;
    for (int c = 0; c < NCHUNK; c++) {
        const size_t o = (size_t)c * SSTATE + t;
        g_Hin[o] = H;
        H = g_P[o] * H + g_hloc[o];
    }
}

__global__ __launch_bounds__(256) void scan_pass3(
    const float* __restrict__ A_log, const float* __restrict__ Dp)
{
    const int wg   = blockIdx.x * 8 + (threadIdx.x >> 5);
    const int lane = threadIdx.x & 31;
    const int c    = wg & (NCHUNK - 1);
    const int rest = wg >> 5;
    const int b    = rest / (DINNER / 2);
    const int dpr  = rest % (DINNER / 2);
    const int n    = lane & 15;
    const int d    = dpr * 2 + (lane >> 4);

    const float A  = -__expf(__ldg(A_log + d * D_STATE + n));
    const float Dd = __ldg(Dp + d);

    const size_t row0 = (size_t)b * L_SEQ + (size_t)c * CHUNK;
    const float* dp = g_delta + row0 * DINNER + d;
    const float* up = g_xc    + row0 * DINNER + d;
    const float* bp = g_xdbl  + row0 * XDBL_N + DT_RANK + n;
    const float* cp = g_xdbl  + row0 * XDBL_N + DT_RANK + D_STATE + n;
    const float* zp = g_xz    + row0 * (2 * DINNER) + DINNER + d;
    __nv_bfloat16* ayp = g_Ay + row0 * (3 * DINNER) + d;

    float h = g_Hin[(size_t)c * SSTATE + ((size_t)b * DINNER + d) * D_STATE + n];

    float pd[4], pu[4], pb[4], pc[4];
#pragma unroll
    for (int g = 0; g < 4; g++) {
        pd[g] = __ldg(dp + g * DINNER);
        pu[g] = __ldg(up + g * DINNER);
        pb[g] = __ldg(bp + g * XDBL_N);
        pc[g] = __ldg(cp + g * XDBL_N);
    }

    for (int t0 = 0; t0 < CHUNK; t0 += 4) {
        float cd[4], cu[4], cb_[4], cc[4];
#pragma unroll
        for (int g = 0; g < 4; g++) { cd[g]=pd[g]; cu[g]=pu[g]; cb_[g]=pb[g]; cc[g]=pc[g]; }
        dp += 4 * DINNER; up += 4 * DINNER; bp += 4 * XDBL_N; cp += 4 * XDBL_N;
        if (t0 + 4 < CHUNK) {
#pragma unroll
            for (int g = 0; g < 4; g++) {
                pd[g] = __ldg(dp + g * DINNER);
                pu[g] = __ldg(up + g * DINNER);
                pb[g] = __ldg(bp + g * XDBL_N);
                pc[g] = __ldg(cp + g * XDBL_N);
            }
        }
#pragma unroll
        for (int g = 0; g < 4; g++) {
            float dt = cd[g], u = cu[g];
            float dA = __expf(dt * A);
            h = fmaf(dA, h, dt * u * cb_[g]);
            float p = h * cc[g];
            p += __shfl_xor_sync(0xffffffffu, p, 1);
            p += __shfl_xor_sync(0xffffffffu, p, 2);
            p += __shfl_xor_sync(0xffffffffu, p, 4);
            p += __shfl_xor_sync(0xffffffffu, p, 8);
            // uniform per half-warp; no divergent block
            float z  = __ldg(zp + g * (2 * DINNER));
            float sz = __fdividef(z, 1.f + __expf(-z));
            float yv = (p + u * Dd) * sz;
            if (n == 0) {
                __nv_bfloat16 hi, lo;
                split_bf16(yv, hi, lo);
                __nv_bfloat16* o = ayp + (size_t)g * (3 * DINNER);
                o[0]          = hi;
                o[DINNER]     = lo;
                o[2 * DINNER] = hi;
            }
        }
        zp += (size_t)4 * 2 * DINNER; ayp += (size_t)4 * 3 * DINNER;
    }
}

// =================================================================
extern "C" void kernel_launch(void* const* d_in, const int* in_sizes, int n_in,
                              void* d_out, int out_size)
{
    const float* hidden = (const float*)d_in[0];
    const float* Win    = (const float*)d_in[1];
    const float* conv_w = (const float*)d_in[2];
    const float* conv_b = (const float*)d_in[3];
    const float* Wx     = (const float*)d_in[4];
    const float* Wdt    = (const float*)d_in[5];
    const float* bdt    = (const float*)d_in[6];
    const float* A_log  = (const float*)d_in[7];
    const float* Dp     = (const float*)d_in[8];
    const float* Wout   = (const float*)d_in[9];
    float* out = (float*)d_out;

    float *xz, *delta;
    __nv_bfloat16 *Ain, *Bin, *Au, *Bx, *Adt, *Bdt, *Ay, *Bout;
    cudaGetSymbolAddress((void**)&xz,    g_xz);
    cudaGetSymbolAddress((void**)&delta, g_delta);
    cudaGetSymbolAddress((void**)&Ain,   g_Ain);
    cudaGetSymbolAddress((void**)&Bin,   g_Bin);
    cudaGetSymbolAddress((void**)&Au,    g_Au);
    cudaGetSymbolAddress((void**)&Bx,    g_Bx);
    cudaGetSymbolAddress((void**)&Adt,   g_Adt);
    cudaGetSymbolAddress((void**)&Bdt,   g_Bdt);
    cudaGetSymbolAddress((void**)&Ay,    g_Ay);
    cudaGetSymbolAddress((void**)&Bout,  g_Bout);

    const int SMEM = 3 * 2 * 128 * 128;   // 98304
    cudaFuncSetAttribute(tc_gemm<0>, cudaFuncAttributeMaxDynamicSharedMemorySize, SMEM);
    cudaFuncSetAttribute(tc_gemm<1>, cudaFuncAttributeMaxDynamicSharedMemorySize, SMEM);
    cudaFuncSetAttribute(tc_gemm<2>, cudaFuncAttributeMaxDynamicSharedMemorySize, SMEM);

    // #1 pack A(hidden)
    pack_a_kernel<<<(unsigned)(((size_t)NROWS * DMODEL + 255) / 256), 256>>>(
        hidden, Ain, NROWS, DMODEL, DMODEL, DMODEL);
    // #2 pack B(Win)
    pack_b_kernel<<<dim3(2*DINNER/32, DMODEL/32), dim3(32,32)>>>(Win, Bin, DMODEL, 2*DINNER, DMODEL, 2*DINNER);
    // #3 pack B(Wdt)
    pack_b_kernel<<<dim3(DINNER/32, 64/32), dim3(32,32)>>>(Wdt, Bdt, DT_RANK, DINNER, 64, DINNER);

    // #4 in-proj GEMM (profiled slot): [8192,768]x[768,3072], K'=2304
    tc_gemm<0><<<dim3(2*DINNER/128, NROWS/128), 256, SMEM>>>(
        Ain, Bin, xz, nullptr, 2*DINNER, 3*DMODEL/64, 3*DMODEL);

    // #5 pack B(Wx)
    pack_b_kernel<<<dim3(128/32, DINNER/32), dim3(32,32)>>>(Wx, Bx, DINNER, XDBL_N, DINNER, 128);
    // #6 conv + silu -> u + packed Au
    conv_silu_kernel<<<dim3(DINNER/256, L_SEQ/64, B_SZ), 256>>>(conv_w, conv_b);
    // #7 x_dbl GEMM (EP=2): [8192,1536]x[1536,80], K'=4608
    tc_gemm<2><<<dim3(1, NROWS/128), 256, SMEM>>>(
        Au, Bx, nullptr, nullptr, XDBL_N, 3*DINNER/64, 3*DINNER);
    // #8 pack B(Wout)
    pack_b_kernel<<<dim3(DMODEL/32, DINNER/32), dim3(32,32)>>>(Wout, Bout, DINNER, DMODEL, DINNER, DMODEL);
    // #9 dt GEMM + softplus: K'=192
    tc_gemm<1><<<dim3(DINNER/128, NROWS/128), 256, SMEM>>>(
        Adt, Bdt, delta, bdt, DINNER, 3, 192);

    // #10-12 chunked scan
    scan_pass1<<<B_SZ * (DINNER/2) * NCHUNK / 8, 256>>>(A_log);
    scan_pass2<<<SSTATE / 256, 256>>>();
    scan_pass3<<<B_SZ * (DINNER/2) * NCHUNK / 8, 256>>>(A_log, Dp);

    // #13 out-proj GEMM: [8192,1536]x[1536,768], K'=4608
    tc_gemm<0><<<dim3(DMODEL/128, NROWS/128), 256, SMEM>>>(
        Ay, Bout, out, nullptr, DMODEL, 3*DINNER/64, 3*DINNER);
}